// round 1
// baseline (speedup 1.0000x reference)
#include <cuda_runtime.h>
#include <math.h>

#define S_LEN    2048
#define D_MODEL  1024
#define N_HEADS  16
#define D_HEAD   64
#define D_MLP    4096
#define N_LAYERS 4
#define N_VOCAB  50257
#define N_TOKENS 4096   // B*S = 2*2048

// -------------------- scratch (no allocation allowed) --------------------
__device__ float g_resid[N_TOKENS * D_MODEL];
__device__ float g_x    [N_TOKENS * D_MODEL];
__device__ float g_q    [N_TOKENS * D_MODEL];
__device__ float g_k    [N_TOKENS * D_MODEL];
__device__ float g_v    [N_TOKENS * D_MODEL];
__device__ float g_z    [N_TOKENS * D_MODEL];
__device__ float g_h    [N_TOKENS * D_MLP];

// -------------------- embedding: resid = W_E[tok] + W_pos[s] -------------
__global__ __launch_bounds__(256) void embed_kernel(
    const int* __restrict__ tok, const float* __restrict__ WE,
    const float* __restrict__ Wp, float* __restrict__ out) {
  int row = blockIdx.x;               // b*S + s
  int s = row & (S_LEN - 1);
  int t = threadIdx.x;                // 256 threads * float4 = 1024
  int token = tok[row];
  float4 e = reinterpret_cast<const float4*>(WE + (size_t)token * D_MODEL)[t];
  float4 p = reinterpret_cast<const float4*>(Wp + (size_t)s * D_MODEL)[t];
  float4 r;
  r.x = e.x + p.x; r.y = e.y + p.y; r.z = e.z + p.z; r.w = e.w + p.w;
  reinterpret_cast<float4*>(out + (size_t)row * D_MODEL)[t] = r;
}

// -------------------- layernorm (one block per row, D=1024) --------------
__global__ __launch_bounds__(256) void ln_kernel(
    const float* __restrict__ in, const float* __restrict__ w,
    const float* __restrict__ b, float* __restrict__ out) {
  int row = blockIdx.x;
  int t = threadIdx.x;
  float4 v = reinterpret_cast<const float4*>(in + (size_t)row * D_MODEL)[t];
  float s  = v.x + v.y + v.z + v.w;
  float ss = v.x*v.x + v.y*v.y + v.z*v.z + v.w*v.w;
#pragma unroll
  for (int off = 16; off; off >>= 1) {
    s  += __shfl_xor_sync(0xffffffffu, s,  off);
    ss += __shfl_xor_sync(0xffffffffu, ss, off);
  }
  __shared__ float shs[8], shss[8];
  int wid = t >> 5;
  if ((t & 31) == 0) { shs[wid] = s; shss[wid] = ss; }
  __syncthreads();
  float tot = 0.f, tots = 0.f;
#pragma unroll
  for (int i = 0; i < 8; i++) { tot += shs[i]; tots += shss[i]; }
  float mean = tot * (1.0f / D_MODEL);
  float var  = tots * (1.0f / D_MODEL) - mean * mean;
  float rstd = rsqrtf(var + 1e-5f);
  float4 wv = reinterpret_cast<const float4*>(w)[t];
  float4 bv = reinterpret_cast<const float4*>(b)[t];
  float4 o;
  o.x = (v.x - mean) * rstd * wv.x + bv.x;
  o.y = (v.y - mean) * rstd * wv.y + bv.y;
  o.z = (v.z - mean) * rstd * wv.z + bv.z;
  o.w = (v.w - mean) * rstd * wv.w + bv.w;
  reinterpret_cast<float4*>(out + (size_t)row * D_MODEL)[t] = o;
}

// -------------------- SGEMM 128x128x8, 256 thr, 8x8 microtile ------------
// C[M,N] = A[M,K] @ B'[K,N] (+bias) (gelu?) (accumulate into C?)
// BMODE 0: B row-major [K,N].
// BMODE 1: QKV weight [H, K, 64]: B[k][j] = W[(j>>6)*K*64 + k*64 + (j&63)].
__device__ __forceinline__ float gelu_new(float x) {
  float u = 0.7978845608028654f * (x + 0.044715f * x * x * x);
  return 0.5f * x * (1.0f + tanhf(u));
}

template<int BMODE, bool BIAS, bool GELU, bool ACCUM>
__global__ __launch_bounds__(256) void sgemm_kernel(
    const float* __restrict__ A, const float* __restrict__ Bw,
    const float* __restrict__ bias, float* __restrict__ C,
    int M, int N, int K) {
  __shared__ __align__(16) float As[8][128];
  __shared__ __align__(16) float Bs[8][128];
  int tid = threadIdx.x;
  int brow = blockIdx.y * 128, bcol = blockIdx.x * 128;
  int arow = tid >> 1, acol = (tid & 1) * 4;        // A tile 128x8, float4
  int bkr  = tid >> 5, bc   = (tid & 31) * 4;       // B tile 8x128
  int tx = tid & 15, ty = tid >> 4;
  float acc[8][8];
#pragma unroll
  for (int i = 0; i < 8; i++)
#pragma unroll
    for (int j = 0; j < 8; j++) acc[i][j] = 0.f;

  const bool n4 = ((N & 3) == 0);
  for (int k0 = 0; k0 < K; k0 += 8) {
    // load A (M,K always multiples of 128/8 here -> no guard)
    float4 a4 = *reinterpret_cast<const float4*>(A + (size_t)(brow + arow) * K + k0 + acol);
    As[acol + 0][arow] = a4.x;
    As[acol + 1][arow] = a4.y;
    As[acol + 2][arow] = a4.z;
    As[acol + 3][arow] = a4.w;
    // load B
    int col = bcol + bc;
    if (BMODE == 1) {
      // within-head float4 (col&63 multiple of 4, head size 64)
      const float* wp = Bw + ((size_t)(col >> 6)) * (size_t)K * 64
                          + (size_t)(k0 + bkr) * 64 + (col & 63);
      float4 b4 = *reinterpret_cast<const float4*>(wp);
      Bs[bkr][bc + 0] = b4.x; Bs[bkr][bc + 1] = b4.y;
      Bs[bkr][bc + 2] = b4.z; Bs[bkr][bc + 3] = b4.w;
    } else {
      const float* bp = Bw + (size_t)(k0 + bkr) * N;
      if (n4 && col + 3 < N) {
        float4 b4 = *reinterpret_cast<const float4*>(bp + col);
        Bs[bkr][bc + 0] = b4.x; Bs[bkr][bc + 1] = b4.y;
        Bs[bkr][bc + 2] = b4.z; Bs[bkr][bc + 3] = b4.w;
      } else {
#pragma unroll
        for (int u = 0; u < 4; u++)
          Bs[bkr][bc + u] = (col + u < N) ? bp[col + u] : 0.f;
      }
    }
    __syncthreads();
#pragma unroll
    for (int kk = 0; kk < 8; kk++) {
      float4 a0 = *reinterpret_cast<const float4*>(&As[kk][ty * 8]);
      float4 a1 = *reinterpret_cast<const float4*>(&As[kk][ty * 8 + 4]);
      float4 b0 = *reinterpret_cast<const float4*>(&Bs[kk][tx * 8]);
      float4 b1 = *reinterpret_cast<const float4*>(&Bs[kk][tx * 8 + 4]);
      float ar[8] = {a0.x, a0.y, a0.z, a0.w, a1.x, a1.y, a1.z, a1.w};
      float br[8] = {b0.x, b0.y, b0.z, b0.w, b1.x, b1.y, b1.z, b1.w};
#pragma unroll
      for (int i = 0; i < 8; i++)
#pragma unroll
        for (int j = 0; j < 8; j++) acc[i][j] += ar[i] * br[j];
    }
    __syncthreads();
  }
  // epilogue
#pragma unroll
  for (int i = 0; i < 8; i++) {
    int r = brow + ty * 8 + i;
#pragma unroll
    for (int j = 0; j < 8; j++) {
      int c = bcol + tx * 8 + j;
      if (c < N) {
        float val = acc[i][j];
        if (BIAS) val += bias[c];
        if (GELU) val = gelu_new(val);
        size_t idx = (size_t)r * N + c;
        if (ACCUM) val += C[idx];
        C[idx] = val;
      }
    }
  }
}

// -------------------- flash attention (fp32, online softmax) -------------
// grid: (S/32, H, B); block 256 = 8 warps; 4 query rows per warp.
// q,k,v,z layout: [B, S, H, DH] contiguous.
__global__ __launch_bounds__(256) void attn_kernel(
    const float* __restrict__ q, const float* __restrict__ k,
    const float* __restrict__ v, float* __restrict__ z) {
  const int b = blockIdx.z, h = blockIdx.y;
  const int q0 = blockIdx.x * 32;
  const int warp = threadIdx.x >> 5, lane = threadIdx.x & 31;
  const int rbase = warp * 4;

  __shared__ float Qs[32][D_HEAD + 1];
  __shared__ float Ks[32][D_HEAD + 1];
  __shared__ float Vs[32][D_HEAD + 1];

  // load Q tile (pre-scaled by 1/sqrt(DH) = 0.125)
  for (int t = threadIdx.x; t < 32 * D_HEAD; t += 256) {
    int r = t >> 6, d = t & 63;
    Qs[r][d] = q[(((size_t)(b * S_LEN + q0 + r)) * N_HEADS + h) * D_HEAD + d] * 0.125f;
  }

  float m[4], lsum[4], acc0[4], acc1[4];
#pragma unroll
  for (int r = 0; r < 4; r++) {
    m[r] = -INFINITY; lsum[r] = 0.f; acc0[r] = 0.f; acc1[r] = 0.f;
  }

  const int kmax = q0 + 31;
  for (int kt = 0; kt <= kmax; kt += 32) {
    __syncthreads();  // previous tile consumed (also covers initial Q load)
    for (int t = threadIdx.x; t < 32 * D_HEAD; t += 256) {
      int r = t >> 6, d = t & 63;
      size_t base = (((size_t)(b * S_LEN + kt + r)) * N_HEADS + h) * D_HEAD + d;
      Ks[r][d] = k[base];
      Vs[r][d] = v[base];
    }
    __syncthreads();

    // scores: lane -> key (kt+lane); 4 rows per warp
    float s[4] = {0.f, 0.f, 0.f, 0.f};
#pragma unroll 16
    for (int d = 0; d < D_HEAD; d++) {
      float kv = Ks[lane][d];
#pragma unroll
      for (int r = 0; r < 4; r++) s[r] += Qs[rbase + r][d] * kv;
    }

    float p[4];
#pragma unroll
    for (int r = 0; r < 4; r++) {
      int qrow = q0 + rbase + r;
      float sv = (kt + lane <= qrow) ? s[r] : -INFINITY;
      float mx = sv;
#pragma unroll
      for (int off = 16; off; off >>= 1)
        mx = fmaxf(mx, __shfl_xor_sync(0xffffffffu, mx, off));
      float mnew = fmaxf(m[r], mx);          // finite from first tile (key 0 valid)
      float corr = __expf(m[r] - mnew);
      p[r] = __expf(sv - mnew);              // exp(-inf)=0 for masked
      m[r] = mnew;
      float psum = p[r];
#pragma unroll
      for (int off = 16; off; off >>= 1)
        psum += __shfl_xor_sync(0xffffffffu, psum, off);
      lsum[r] = lsum[r] * corr + psum;
      acc0[r] *= corr; acc1[r] *= corr;
    }
    // acc += P @ V  (lane owns output dims lane and lane+32)
#pragma unroll 8
    for (int i = 0; i < 32; i++) {
      float v0 = Vs[i][lane], v1 = Vs[i][lane + 32];
#pragma unroll
      for (int r = 0; r < 4; r++) {
        float pi = __shfl_sync(0xffffffffu, p[r], i);
        acc0[r] += pi * v0;
        acc1[r] += pi * v1;
      }
    }
  }

#pragma unroll
  for (int r = 0; r < 4; r++) {
    int qrow = q0 + rbase + r;
    size_t base = (((size_t)(b * S_LEN + qrow)) * N_HEADS + h) * D_HEAD;
    float inv = 1.0f / lsum[r];
    z[base + lane]      = acc0[r] * inv;
    z[base + lane + 32] = acc1[r] * inv;
  }
}

// -------------------- driver --------------------
extern "C" void kernel_launch(void* const* d_in, const int* in_sizes, int n_in,
                              void* d_out, int out_size) {
  const int*   tokens = (const int*)  d_in[0];
  const float* W_E    = (const float*)d_in[1];
  const float* W_pos  = (const float*)d_in[2];
  const float* ln1_w  = (const float*)d_in[3];
  const float* ln1_b  = (const float*)d_in[4];
  const float* W_Q    = (const float*)d_in[5];
  const float* b_Q    = (const float*)d_in[6];
  const float* W_K    = (const float*)d_in[7];
  const float* b_K    = (const float*)d_in[8];
  const float* W_V    = (const float*)d_in[9];
  const float* b_V    = (const float*)d_in[10];
  const float* W_O    = (const float*)d_in[11];
  const float* b_O    = (const float*)d_in[12];
  const float* ln2_w  = (const float*)d_in[13];
  const float* ln2_b  = (const float*)d_in[14];
  const float* W_in   = (const float*)d_in[15];
  const float* b_in   = (const float*)d_in[16];
  const float* W_out  = (const float*)d_in[17];
  const float* b_out  = (const float*)d_in[18];
  const float* lnf_w  = (const float*)d_in[19];
  const float* lnf_b  = (const float*)d_in[20];
  const float* W_U    = (const float*)d_in[21];
  const float* b_U    = (const float*)d_in[22];
  float* out = (float*)d_out;

  float *resid, *x, *q, *k, *v, *z, *hbuf;
  cudaGetSymbolAddress((void**)&resid, g_resid);
  cudaGetSymbolAddress((void**)&x,     g_x);
  cudaGetSymbolAddress((void**)&q,     g_q);
  cudaGetSymbolAddress((void**)&k,     g_k);
  cudaGetSymbolAddress((void**)&v,     g_v);
  cudaGetSymbolAddress((void**)&z,     g_z);
  cudaGetSymbolAddress((void**)&hbuf,  g_h);

  embed_kernel<<<N_TOKENS, 256>>>(tokens, W_E, W_pos, resid);

  dim3 gD(D_MODEL / 128, N_TOKENS / 128);   // (8,32)
  dim3 gM(D_MLP / 128,  N_TOKENS / 128);    // (32,32)
  dim3 gV((N_VOCAB + 127) / 128, N_TOKENS / 128);
  dim3 gA(S_LEN / 32, N_HEADS, 2);

  for (int l = 0; l < N_LAYERS; l++) {
    size_t wqkv = (size_t)l * N_HEADS * D_MODEL * D_HEAD;   // 1048576
    size_t wmlp = (size_t)l * D_MODEL * D_MLP;              // 4194304
    const float* l1w = ln1_w + (size_t)l * D_MODEL;
    const float* l1b = ln1_b + (size_t)l * D_MODEL;
    const float* l2w = ln2_w + (size_t)l * D_MODEL;
    const float* l2b = ln2_b + (size_t)l * D_MODEL;

    ln_kernel<<<N_TOKENS, 256>>>(resid, l1w, l1b, x);
    sgemm_kernel<1, true, false, false><<<gD, 256>>>(x, W_Q + wqkv, b_Q + (size_t)l * D_MODEL, q, N_TOKENS, D_MODEL, D_MODEL);
    sgemm_kernel<1, true, false, false><<<gD, 256>>>(x, W_K + wqkv, b_K + (size_t)l * D_MODEL, k, N_TOKENS, D_MODEL, D_MODEL);
    sgemm_kernel<1, true, false, false><<<gD, 256>>>(x, W_V + wqkv, b_V + (size_t)l * D_MODEL, v, N_TOKENS, D_MODEL, D_MODEL);

    attn_kernel<<<gA, 256>>>(q, k, v, z);

    // resid += z @ W_O + b_O   (W_O[l] is [H*DH, D] row-major when flattened)
    sgemm_kernel<0, true, false, true><<<gD, 256>>>(z, W_O + wqkv, b_O + (size_t)l * D_MODEL, resid, N_TOKENS, D_MODEL, D_MODEL);

    ln_kernel<<<N_TOKENS, 256>>>(resid, l2w, l2b, x);
    // h = gelu(x @ W_in + b_in)
    sgemm_kernel<0, true, true, false><<<gM, 256>>>(x, W_in + wmlp, b_in + (size_t)l * D_MLP, hbuf, N_TOKENS, D_MLP, D_MODEL);
    // resid += h @ W_out + b_out
    sgemm_kernel<0, true, false, true><<<gD, 256>>>(hbuf, W_out + wmlp, b_out + (size_t)l * D_MODEL, resid, N_TOKENS, D_MODEL, D_MLP);
  }

  ln_kernel<<<N_TOKENS, 256>>>(resid, lnf_w, lnf_b, x);
  sgemm_kernel<0, true, false, false><<<gV, 256>>>(x, W_U, b_U, out, N_TOKENS, N_VOCAB, D_MODEL);
}

// round 3
// speedup vs baseline: 2.6097x; 2.6097x over previous
#include <cuda_runtime.h>
#include <cstdint>
#include <math.h>

#define S_LEN    2048
#define D_MODEL  1024
#define N_HEADS  16
#define D_HEAD   64
#define D_MLP    4096
#define N_LAYERS 4
#define N_VOCAB  50257
#define N_TOKENS 4096   // B*S

// -------------------- scratch --------------------
__device__ float g_resid[N_TOKENS * D_MODEL];
__device__ float g_x    [N_TOKENS * D_MODEL];
__device__ float g_q    [N_TOKENS * D_MODEL];
__device__ float g_k    [N_TOKENS * D_MODEL];
__device__ float g_v    [N_TOKENS * D_MODEL];
__device__ float g_z    [N_TOKENS * D_MODEL];
__device__ float g_h    [N_TOKENS * D_MLP];

// -------------------- embedding --------------------
__global__ __launch_bounds__(256) void embed_kernel(
    const int* __restrict__ tok, const float* __restrict__ WE,
    const float* __restrict__ Wp, float* __restrict__ out) {
  int row = blockIdx.x;
  int s = row & (S_LEN - 1);
  int t = threadIdx.x;
  int token = tok[row];
  float4 e = reinterpret_cast<const float4*>(WE + (size_t)token * D_MODEL)[t];
  float4 p = reinterpret_cast<const float4*>(Wp + (size_t)s * D_MODEL)[t];
  float4 r;
  r.x = e.x + p.x; r.y = e.y + p.y; r.z = e.z + p.z; r.w = e.w + p.w;
  reinterpret_cast<float4*>(out + (size_t)row * D_MODEL)[t] = r;
}

// -------------------- layernorm --------------------
__global__ __launch_bounds__(256) void ln_kernel(
    const float* __restrict__ in, const float* __restrict__ w,
    const float* __restrict__ b, float* __restrict__ out) {
  int row = blockIdx.x;
  int t = threadIdx.x;
  float4 v = reinterpret_cast<const float4*>(in + (size_t)row * D_MODEL)[t];
  float s  = v.x + v.y + v.z + v.w;
  float ss = v.x*v.x + v.y*v.y + v.z*v.z + v.w*v.w;
#pragma unroll
  for (int off = 16; off; off >>= 1) {
    s  += __shfl_xor_sync(0xffffffffu, s,  off);
    ss += __shfl_xor_sync(0xffffffffu, ss, off);
  }
  __shared__ float shs[8], shss[8];
  int wid = t >> 5;
  if ((t & 31) == 0) { shs[wid] = s; shss[wid] = ss; }
  __syncthreads();
  float tot = 0.f, tots = 0.f;
#pragma unroll
  for (int i = 0; i < 8; i++) { tot += shs[i]; tots += shss[i]; }
  float mean = tot * (1.0f / D_MODEL);
  float var  = tots * (1.0f / D_MODEL) - mean * mean;
  float rstd = rsqrtf(var + 1e-5f);
  float4 wv = reinterpret_cast<const float4*>(w)[t];
  float4 bv = reinterpret_cast<const float4*>(b)[t];
  float4 o;
  o.x = (v.x - mean) * rstd * wv.x + bv.x;
  o.y = (v.y - mean) * rstd * wv.y + bv.y;
  o.z = (v.z - mean) * rstd * wv.z + bv.z;
  o.w = (v.w - mean) * rstd * wv.w + bv.w;
  reinterpret_cast<float4*>(out + (size_t)row * D_MODEL)[t] = o;
}

// -------------------- TF32 tensor-core GEMM --------------------
// C[M,N] = A[M,K] @ B[K,N] (+bias) (gelu?) (+=C?)
// Block tile 128x128x32, 8 warps, warp tile 64x32 via mma.m16n8k8.tf32.
// BMODE 0: B row-major [K,N].  BMODE 1: QKV weight [H, K, 64].
// NAL: true if B rows are 16B-aligned for all k (N*4 % 16 == 0 or BMODE 1).
__device__ __forceinline__ float gelu_new(float x) {
  float u = 0.7978845608028654f * (x + 0.044715f * x * x * x);
  return 0.5f * x * (1.0f + tanhf(u));
}

#define CVT_TF32(d, s) asm("cvt.rna.tf32.f32 %0, %1;" : "=r"(d) : "f"(s))

#define A_LD 36           // padded row stride (floats) of As: bank = 4g+t (conflict-free)
#define B_LD 136          // padded row stride of Bs: bank = 8t+g (conflict-free)
#define A_BUF (128 * A_LD)
#define B_BUF (32 * B_LD)
#define GEMM_SMEM_BYTES ((2 * A_BUF + 2 * B_BUF) * 4)

__device__ __forceinline__ void cp_async16(uint32_t dst, const void* src) {
  asm volatile("cp.async.ca.shared.global [%0], [%1], 16;\n" :: "r"(dst), "l"(src));
}
__device__ __forceinline__ void cp_async4_guard(uint32_t dst, const void* src, int nbytes) {
  asm volatile("cp.async.ca.shared.global [%0], [%1], 4, %2;\n" :: "r"(dst), "l"(src), "r"(nbytes));
}

template<int BMODE, bool NAL>
__device__ __forceinline__ void stage_tile(
    const float* __restrict__ A, const float* __restrict__ Bw,
    float* As, float* Bs, int brow, int bcol, int k0, int N, int K, int tid) {
  // A tile: 128 rows x 32 cols (A is always 16B-aligned: K multiple of 32)
  {
    int r = tid >> 3, c = (tid & 7) * 4;
    const float* src = A + (size_t)(brow + r) * K + k0 + c;
    uint32_t dst = (uint32_t)__cvta_generic_to_shared(As + r * A_LD + c);
#pragma unroll
    for (int it = 0; it < 4; it++) {
      cp_async16(dst, src);
      src += (size_t)32 * K;
      dst += 32 * A_LD * 4;
    }
  }
  // B tile: 32 rows (k) x 128 cols (n)
  {
    int kr = tid >> 5, c = (tid & 31) * 4;
    int col = bcol + c;
    uint32_t dst = (uint32_t)__cvta_generic_to_shared(Bs + kr * B_LD + c);
    if (BMODE == 1) {
      const float* src = Bw + ((size_t)(col >> 6)) * (size_t)K * 64
                            + (size_t)(k0 + kr) * 64 + (col & 63);
#pragma unroll
      for (int it = 0; it < 4; it++) {
        cp_async16(dst, src);
        src += 8 * 64;
        dst += 8 * B_LD * 4;
      }
    } else if (NAL) {
      const float* src = Bw + (size_t)(k0 + kr) * N + col;
#pragma unroll
      for (int it = 0; it < 4; it++) {
        cp_async16(dst, src);
        src += (size_t)8 * N;
        dst += 8 * B_LD * 4;
      }
    } else {
      // N not 16B-friendly (vocab GEMM, N odd): 4B copies with clamp + zero-fill
#pragma unroll
      for (int it = 0; it < 4; it++) {
        const float* rowp = Bw + (size_t)(k0 + kr + it * 8) * N;
        uint32_t d2 = dst + it * 8 * B_LD * 4;
#pragma unroll
        for (int u = 0; u < 4; u++) {
          int cc = col + u;
          int ok = (cc < N);
          const float* src = rowp + (ok ? cc : 0);
          cp_async4_guard(d2 + 4 * u, src, ok ? 4 : 0);
        }
      }
    }
  }
  asm volatile("cp.async.commit_group;\n" ::: "memory");
}

template<int BMODE, bool NAL, bool GELU, bool ACCUM>
__global__ __launch_bounds__(256) void tgemm_kernel(
    const float* __restrict__ A, const float* __restrict__ Bw,
    const float* __restrict__ bias, float* __restrict__ C,
    int M, int N, int K) {
  extern __shared__ float smem[];
  float* As = smem;                 // 2 buffers
  float* Bs = smem + 2 * A_BUF;

  const int tid  = threadIdx.x;
  const int lane = tid & 31, warp = tid >> 5;
  const int wm = (warp >> 2) * 64;  // warp M offset (2 warps in M)
  const int wn = (warp & 3) * 32;   // warp N offset (4 warps in N)
  const int g = lane >> 2, t = lane & 3;
  const int brow = blockIdx.y * 128, bcol = blockIdx.x * 128;

  float acc[16][4];
#pragma unroll
  for (int i = 0; i < 16; i++)
#pragma unroll
    for (int j = 0; j < 4; j++) acc[i][j] = 0.f;

  const int nk = K / 32;
  stage_tile<BMODE, NAL>(A, Bw, As, Bs, brow, bcol, 0, N, K, tid);

  for (int kb = 0; kb < nk; kb++) {
    asm volatile("cp.async.wait_group 0;\n" ::: "memory");
    __syncthreads();
    if (kb + 1 < nk) {
      int nb = (kb + 1) & 1;
      stage_tile<BMODE, NAL>(A, Bw, As + nb * A_BUF, Bs + nb * B_BUF,
                             brow, bcol, (kb + 1) * 32, N, K, tid);
    }
    const float* a_s = As + (kb & 1) * A_BUF;
    const float* b_s = Bs + (kb & 1) * B_BUF;

#pragma unroll
    for (int ik = 0; ik < 4; ik++) {
      uint32_t af[4][4], bf[4][2];
#pragma unroll
      for (int im = 0; im < 4; im++) {
        const float* ap = a_s + (wm + im * 16 + g) * A_LD + ik * 8 + t;
        CVT_TF32(af[im][0], ap[0]);
        CVT_TF32(af[im][1], ap[8 * A_LD]);
        CVT_TF32(af[im][2], ap[4]);
        CVT_TF32(af[im][3], ap[8 * A_LD + 4]);
      }
#pragma unroll
      for (int in = 0; in < 4; in++) {
        const float* bp = b_s + (ik * 8 + t) * B_LD + wn + in * 8 + g;
        CVT_TF32(bf[in][0], bp[0]);
        CVT_TF32(bf[in][1], bp[4 * B_LD]);
      }
#pragma unroll
      for (int im = 0; im < 4; im++)
#pragma unroll
        for (int in = 0; in < 4; in++) {
          float* c = acc[im * 4 + in];
          asm volatile(
            "mma.sync.aligned.m16n8k8.row.col.f32.tf32.tf32.f32 "
            "{%0,%1,%2,%3}, {%4,%5,%6,%7}, {%8,%9}, {%0,%1,%2,%3};\n"
            : "+f"(c[0]), "+f"(c[1]), "+f"(c[2]), "+f"(c[3])
            : "r"(af[im][0]), "r"(af[im][1]), "r"(af[im][2]), "r"(af[im][3]),
              "r"(bf[in][0]), "r"(bf[in][1]));
        }
    }
    __syncthreads();
  }

  // epilogue: c0:(g,2t) c1:(g,2t+1) c2:(g+8,2t) c3:(g+8,2t+1) per 16x8 tile
#pragma unroll
  for (int im = 0; im < 4; im++) {
#pragma unroll
    for (int in = 0; in < 4; in++) {
      const float* c = acc[im * 4 + in];
      int r0 = brow + wm + im * 16 + g;
      int c0 = bcol + wn + in * 8 + 2 * t;
#pragma unroll
      for (int u = 0; u < 4; u++) {
        int r = r0 + (u >> 1) * 8;
        int cc = c0 + (u & 1);
        if (cc < N) {
          float val = c[u] + bias[cc];
          if (GELU) val = gelu_new(val);
          size_t idx = (size_t)r * N + cc;
          if (ACCUM) val += C[idx];
          C[idx] = val;
        }
      }
    }
  }
}

// -------------------- flash attention (fp32) --------------------
__global__ __launch_bounds__(256) void attn_kernel(
    const float* __restrict__ q, const float* __restrict__ k,
    const float* __restrict__ v, float* __restrict__ z) {
  const int b = blockIdx.z, h = blockIdx.y;
  const int q0 = blockIdx.x * 32;
  const int warp = threadIdx.x >> 5, lane = threadIdx.x & 31;
  const int rbase = warp * 4;

  __shared__ float Qs[32][D_HEAD + 1];
  __shared__ float Ks[32][D_HEAD + 1];
  __shared__ float Vs[32][D_HEAD + 1];

  for (int t = threadIdx.x; t < 32 * D_HEAD; t += 256) {
    int r = t >> 6, d = t & 63;
    Qs[r][d] = q[(((size_t)(b * S_LEN + q0 + r)) * N_HEADS + h) * D_HEAD + d] * 0.125f;
  }

  float m[4], lsum[4], acc0[4], acc1[4];
#pragma unroll
  for (int r = 0; r < 4; r++) {
    m[r] = -INFINITY; lsum[r] = 0.f; acc0[r] = 0.f; acc1[r] = 0.f;
  }

  const int kmax = q0 + 31;
  for (int kt = 0; kt <= kmax; kt += 32) {
    __syncthreads();
    for (int t = threadIdx.x; t < 32 * D_HEAD; t += 256) {
      int r = t >> 6, d = t & 63;
      size_t base = (((size_t)(b * S_LEN + kt + r)) * N_HEADS + h) * D_HEAD + d;
      Ks[r][d] = k[base];
      Vs[r][d] = v[base];
    }
    __syncthreads();

    float s[4] = {0.f, 0.f, 0.f, 0.f};
#pragma unroll 16
    for (int d = 0; d < D_HEAD; d++) {
      float kv = Ks[lane][d];
#pragma unroll
      for (int r = 0; r < 4; r++) s[r] += Qs[rbase + r][d] * kv;
    }

    float p[4];
#pragma unroll
    for (int r = 0; r < 4; r++) {
      int qrow = q0 + rbase + r;
      float sv = (kt + lane <= qrow) ? s[r] : -INFINITY;
      float mx = sv;
#pragma unroll
      for (int off = 16; off; off >>= 1)
        mx = fmaxf(mx, __shfl_xor_sync(0xffffffffu, mx, off));
      float mnew = fmaxf(m[r], mx);
      float corr = __expf(m[r] - mnew);
      p[r] = __expf(sv - mnew);
      m[r] = mnew;
      float psum = p[r];
#pragma unroll
      for (int off = 16; off; off >>= 1)
        psum += __shfl_xor_sync(0xffffffffu, psum, off);
      lsum[r] = lsum[r] * corr + psum;
      acc0[r] *= corr; acc1[r] *= corr;
    }
#pragma unroll 8
    for (int i = 0; i < 32; i++) {
      float v0 = Vs[i][lane], v1 = Vs[i][lane + 32];
#pragma unroll
      for (int r = 0; r < 4; r++) {
        float pi = __shfl_sync(0xffffffffu, p[r], i);
        acc0[r] += pi * v0;
        acc1[r] += pi * v1;
      }
    }
  }

#pragma unroll
  for (int r = 0; r < 4; r++) {
    int qrow = q0 + rbase + r;
    size_t base = (((size_t)(b * S_LEN + qrow)) * N_HEADS + h) * D_HEAD;
    float inv = 1.0f / lsum[r];
    z[base + lane]      = acc0[r] * inv;
    z[base + lane + 32] = acc1[r] * inv;
  }
}

// -------------------- driver --------------------
template<int BMODE, bool NAL, bool GELU, bool ACCUM>
static void launch_gemm(const float* A, const float* B, const float* bias,
                        float* C, int M, int N, int K, cudaStream_t st = 0) {
  cudaFuncSetAttribute(tgemm_kernel<BMODE, NAL, GELU, ACCUM>,
                       cudaFuncAttributeMaxDynamicSharedMemorySize, GEMM_SMEM_BYTES);
  dim3 grid((N + 127) / 128, M / 128);
  tgemm_kernel<BMODE, NAL, GELU, ACCUM><<<grid, 256, GEMM_SMEM_BYTES, st>>>(A, B, bias, C, M, N, K);
}

extern "C" void kernel_launch(void* const* d_in, const int* in_sizes, int n_in,
                              void* d_out, int out_size) {
  const int*   tokens = (const int*)  d_in[0];
  const float* W_E    = (const float*)d_in[1];
  const float* W_pos  = (const float*)d_in[2];
  const float* ln1_w  = (const float*)d_in[3];
  const float* ln1_b  = (const float*)d_in[4];
  const float* W_Q    = (const float*)d_in[5];
  const float* b_Q    = (const float*)d_in[6];
  const float* W_K    = (const float*)d_in[7];
  const float* b_K    = (const float*)d_in[8];
  const float* W_V    = (const float*)d_in[9];
  const float* b_V    = (const float*)d_in[10];
  const float* W_O    = (const float*)d_in[11];
  const float* b_O    = (const float*)d_in[12];
  const float* ln2_w  = (const float*)d_in[13];
  const float* ln2_b  = (const float*)d_in[14];
  const float* W_in   = (const float*)d_in[15];
  const float* b_in   = (const float*)d_in[16];
  const float* W_out  = (const float*)d_in[17];
  const float* b_out  = (const float*)d_in[18];
  const float* lnf_w  = (const float*)d_in[19];
  const float* lnf_b  = (const float*)d_in[20];
  const float* W_U    = (const float*)d_in[21];
  const float* b_U    = (const float*)d_in[22];
  float* out = (float*)d_out;

  float *resid, *x, *q, *k, *v, *z, *hbuf;
  cudaGetSymbolAddress((void**)&resid, g_resid);
  cudaGetSymbolAddress((void**)&x,     g_x);
  cudaGetSymbolAddress((void**)&q,     g_q);
  cudaGetSymbolAddress((void**)&k,     g_k);
  cudaGetSymbolAddress((void**)&v,     g_v);
  cudaGetSymbolAddress((void**)&z,     g_z);
  cudaGetSymbolAddress((void**)&hbuf,  g_h);

  embed_kernel<<<N_TOKENS, 256>>>(tokens, W_E, W_pos, resid);

  dim3 gA(S_LEN / 32, N_HEADS, 2);

  for (int l = 0; l < N_LAYERS; l++) {
    size_t wqkv = (size_t)l * N_HEADS * D_MODEL * D_HEAD;
    size_t wmlp = (size_t)l * D_MODEL * D_MLP;
    const float* l1w = ln1_w + (size_t)l * D_MODEL;
    const float* l1b = ln1_b + (size_t)l * D_MODEL;
    const float* l2w = ln2_w + (size_t)l * D_MODEL;
    const float* l2b = ln2_b + (size_t)l * D_MODEL;

    ln_kernel<<<N_TOKENS, 256>>>(resid, l1w, l1b, x);
    launch_gemm<1, true, false, false>(x, W_Q + wqkv, b_Q + (size_t)l * D_MODEL, q, N_TOKENS, D_MODEL, D_MODEL);
    launch_gemm<1, true, false, false>(x, W_K + wqkv, b_K + (size_t)l * D_MODEL, k, N_TOKENS, D_MODEL, D_MODEL);
    launch_gemm<1, true, false, false>(x, W_V + wqkv, b_V + (size_t)l * D_MODEL, v, N_TOKENS, D_MODEL, D_MODEL);

    attn_kernel<<<gA, 256>>>(q, k, v, z);

    launch_gemm<0, true, false, true>(z, W_O + wqkv, b_O + (size_t)l * D_MODEL, resid, N_TOKENS, D_MODEL, D_MODEL);

    ln_kernel<<<N_TOKENS, 256>>>(resid, l2w, l2b, x);
    launch_gemm<0, true, true,  false>(x, W_in + wmlp, b_in + (size_t)l * D_MLP, hbuf, N_TOKENS, D_MLP, D_MODEL);
    launch_gemm<0, true, false, true >(hbuf, W_out + wmlp, b_out + (size_t)l * D_MODEL, resid, N_TOKENS, D_MODEL, D_MLP);
  }

  ln_kernel<<<N_TOKENS, 256>>>(resid, lnf_w, lnf_b, x);
  // N_VOCAB odd -> B rows not 16B aligned -> NAL=false scalar cp.async path
  launch_gemm<0, false, false, false>(x, W_U, b_U, out, N_TOKENS, N_VOCAB, D_MODEL);
}

// round 6
// speedup vs baseline: 3.8464x; 1.4739x over previous
#include <cuda_runtime.h>
#include <cuda_fp16.h>
#include <cstdint>
#include <math.h>

#define S_LEN    2048
#define D_MODEL  1024
#define N_HEADS  16
#define D_HEAD   64
#define D_MLP    4096
#define N_LAYERS 4
#define N_VOCAB  50257
#define N_VOCAB_PAD 50432   // 394*128
#define N_TOKENS 4096       // B*S
#define QKV_N    3072

// -------------------- scratch --------------------
__device__ float  g_resid[N_TOKENS * D_MODEL];
__device__ __half g_xh   [N_TOKENS * D_MODEL];
__device__ float  g_qkv  [N_TOKENS * QKV_N];
__device__ __half g_zh   [N_TOKENS * D_MODEL];
__device__ __half g_hh   [N_TOKENS * D_MLP];
// fp16 weights, B layout [K][N] row-major (padded N where needed)
__device__ __half g_wqkv [N_LAYERS * D_MODEL * QKV_N];
__device__ float  g_bqkv [N_LAYERS * QKV_N];
__device__ __half g_wo   [N_LAYERS * D_MODEL * D_MODEL];
__device__ __half g_win  [N_LAYERS * D_MODEL * D_MLP];
__device__ __half g_wout [N_LAYERS * D_MLP * D_MODEL];
__device__ __half g_wu   [D_MODEL * N_VOCAB_PAD];

// -------------------- helpers --------------------
__device__ __forceinline__ float gelu_new(float x) {
  float u = 0.7978845608028654f * (x + 0.044715f * x * x * x);
  return 0.5f * x * (1.0f + tanhf(u));
}
__device__ __forceinline__ void ldsm_x4(uint32_t (&r)[4], uint32_t addr) {
  asm volatile("ldmatrix.sync.aligned.m8n8.x4.shared.b16 {%0,%1,%2,%3}, [%4];"
    : "=r"(r[0]), "=r"(r[1]), "=r"(r[2]), "=r"(r[3]) : "r"(addr));
}
__device__ __forceinline__ void ldsm_x4_t(uint32_t (&r)[4], uint32_t addr) {
  asm volatile("ldmatrix.sync.aligned.m8n8.x4.trans.shared.b16 {%0,%1,%2,%3}, [%4];"
    : "=r"(r[0]), "=r"(r[1]), "=r"(r[2]), "=r"(r[3]) : "r"(addr));
}
__device__ __forceinline__ void mma_f16(float (&c)[4], const uint32_t (&a)[4],
                                        const uint32_t b0, const uint32_t b1) {
  asm volatile("mma.sync.aligned.m16n8k16.row.col.f32.f16.f16.f32 "
    "{%0,%1,%2,%3}, {%4,%5,%6,%7}, {%8,%9}, {%0,%1,%2,%3};"
    : "+f"(c[0]), "+f"(c[1]), "+f"(c[2]), "+f"(c[3])
    : "r"(a[0]), "r"(a[1]), "r"(a[2]), "r"(a[3]), "r"(b0), "r"(b1));
}
__device__ __forceinline__ void cp_async16(uint32_t dst, const void* src) {
  asm volatile("cp.async.cg.shared.global [%0], [%1], 16;\n" :: "r"(dst), "l"(src));
}

// -------------------- weight conversion --------------------
__global__ __launch_bounds__(256) void conv_qkv(
    const float* __restrict__ WQ, const float* __restrict__ WK,
    const float* __restrict__ WV, __half* __restrict__ out) {
  size_t i = (size_t)blockIdx.x * 256 + threadIdx.x;   // L*1024*3072 total
  int n = (int)(i % QKV_N);
  size_t lk = i / QKV_N;
  int k = (int)(lk % D_MODEL);
  int l = (int)(lk / D_MODEL);
  int which = n >> 10, nn = n & 1023;
  int h = nn >> 6, dh = nn & 63;
  const float* W = (which == 0) ? WQ : ((which == 1) ? WK : WV);
  out[i] = __float2half(W[(((size_t)l * N_HEADS + h) * D_MODEL + k) * D_HEAD + dh]);
}
__global__ __launch_bounds__(256) void pack_bias_qkv(
    const float* __restrict__ bq, const float* __restrict__ bk,
    const float* __restrict__ bv, float* __restrict__ out) {
  int i = blockIdx.x * 256 + threadIdx.x;   // L*3072
  int n = i % QKV_N, l = i / QKV_N;
  const float* s = (n < 1024) ? bq : ((n < 2048) ? bk : bv);
  out[i] = s[l * 1024 + (n & 1023)];
}
__global__ __launch_bounds__(256) void conv_plain(
    const float* __restrict__ in, __half* __restrict__ out, int N, int Npad) {
  size_t i = (size_t)blockIdx.x * 256 + threadIdx.x;   // K*Npad total
  int n = (int)(i % Npad);
  size_t k = i / Npad;
  out[i] = __float2half((n < N) ? in[k * N + n] : 0.f);
}

// -------------------- embedding --------------------
__global__ __launch_bounds__(256) void embed_kernel(
    const int* __restrict__ tok, const float* __restrict__ WE,
    const float* __restrict__ Wp, float* __restrict__ out) {
  int row = blockIdx.x;
  int s = row & (S_LEN - 1);
  int t = threadIdx.x;
  int token = tok[row];
  float4 e = reinterpret_cast<const float4*>(WE + (size_t)token * D_MODEL)[t];
  float4 p = reinterpret_cast<const float4*>(Wp + (size_t)s * D_MODEL)[t];
  float4 r;
  r.x = e.x + p.x; r.y = e.y + p.y; r.z = e.z + p.z; r.w = e.w + p.w;
  reinterpret_cast<float4*>(out + (size_t)row * D_MODEL)[t] = r;
}

// -------------------- layernorm (fp32 in, fp16 out) --------------------
__global__ __launch_bounds__(256) void ln_kernel(
    const float* __restrict__ in, const float* __restrict__ w,
    const float* __restrict__ b, __half* __restrict__ out) {
  int row = blockIdx.x;
  int t = threadIdx.x;
  float4 v = reinterpret_cast<const float4*>(in + (size_t)row * D_MODEL)[t];
  float s  = v.x + v.y + v.z + v.w;
  float ss = v.x*v.x + v.y*v.y + v.z*v.z + v.w*v.w;
#pragma unroll
  for (int off = 16; off; off >>= 1) {
    s  += __shfl_xor_sync(0xffffffffu, s,  off);
    ss += __shfl_xor_sync(0xffffffffu, ss, off);
  }
  __shared__ float shs[8], shss[8];
  int wid = t >> 5;
  if ((t & 31) == 0) { shs[wid] = s; shss[wid] = ss; }
  __syncthreads();
  float tot = 0.f, tots = 0.f;
#pragma unroll
  for (int i = 0; i < 8; i++) { tot += shs[i]; tots += shss[i]; }
  float mean = tot * (1.0f / D_MODEL);
  float var  = tots * (1.0f / D_MODEL) - mean * mean;
  float rstd = rsqrtf(var + 1e-5f);
  float4 wv = reinterpret_cast<const float4*>(w)[t];
  float4 bv = reinterpret_cast<const float4*>(b)[t];
  float ox = (v.x - mean) * rstd * wv.x + bv.x;
  float oy = (v.y - mean) * rstd * wv.y + bv.y;
  float oz = (v.z - mean) * rstd * wv.z + bv.z;
  float ow = (v.w - mean) * rstd * wv.w + bv.w;
  __half2* o2 = reinterpret_cast<__half2*>(out + (size_t)row * D_MODEL);
  o2[2 * t]     = __floats2half2_rn(ox, oy);
  o2[2 * t + 1] = __floats2half2_rn(oz, ow);
}

// -------------------- FP16 tensor-core GEMM --------------------
// C[M,Nstore] = A_h[M,K] @ B_h[K,NB] (+bias fp32) (gelu?) (accum fp32?) (out half?)
// Block 128x128, k-tile 64, 8 warps (warp tile 64x32), 3-stage cp.async.
#define KT        64
#define LDA_B     144     // bytes per A smem row (72 halves)
#define LDB_B     272     // bytes per B smem row (136 halves)
#define A_BYTES   (128 * LDA_B)   // 18432
#define B_BYTES   (KT * LDB_B)    // 17408
#define STAGE_B   (A_BYTES + B_BYTES)
#define NSTAGES   3
#define GEMM_SMEM (NSTAGES * STAGE_B)

template<bool GELU, bool ACCUM, bool OUTH>
__global__ __launch_bounds__(256) void hgemm(
    const __half* __restrict__ A, const __half* __restrict__ B,
    const float* __restrict__ bias, void* __restrict__ Cv,
    int M, int K, int NB, int Nstore) {
  extern __shared__ __align__(16) char smem[];
  const uint32_t sm = (uint32_t)__cvta_generic_to_shared(smem);

  const int tid  = threadIdx.x;
  const int lane = tid & 31, warp = tid >> 5;
  const int wm = (warp >> 2) * 64;   // 2 warps in M
  const int wn = (warp & 3) * 32;    // 4 warps in N
  const int g = lane >> 2, t = lane & 3;
  const int brow = blockIdx.y * 128, bcol = blockIdx.x * 128;
  const uint32_t laneRow = lane & 15, laneHi = lane >> 4;

  float acc[16][4];
#pragma unroll
  for (int i = 0; i < 16; i++)
#pragma unroll
    for (int j = 0; j < 4; j++) acc[i][j] = 0.f;

  const int NT = K / KT;

  auto stage = [&](int tt) {
    const int k0 = tt * KT;
    const uint32_t sA = sm + (uint32_t)(tt % NSTAGES) * STAGE_B;
    const uint32_t sB = sA + A_BYTES;
    // A: 128 rows x 64 halves (8 chunks of 8 halves)
    {
      int slot = tid;
#pragma unroll
      for (int i = 0; i < 4; i++) {
        int r = slot >> 3, ch = slot & 7;
        cp_async16(sA + (uint32_t)r * LDA_B + ch * 16,
                   A + (size_t)(brow + r) * K + k0 + ch * 8);
        slot += 256;
      }
    }
    // B: 64 rows x 128 halves (16 chunks)
    {
      int slot = tid;
#pragma unroll
      for (int i = 0; i < 4; i++) {
        int r = slot >> 4, ch = slot & 15;
        cp_async16(sB + (uint32_t)r * LDB_B + ch * 16,
                   B + (size_t)(k0 + r) * NB + bcol + ch * 8);
        slot += 256;
      }
    }
    asm volatile("cp.async.commit_group;\n" ::: "memory");
  };

  stage(0);
  if (NT > 1) stage(1);

  for (int tt = 0; tt < NT; tt++) {
    // tail-safe wait: at the last tile only group NT-1 is pending, so
    // wait_group 1 would NOT drain it -> must fully drain there.
    if (tt + 1 < NT) {
      asm volatile("cp.async.wait_group 1;\n" ::: "memory");
    } else {
      asm volatile("cp.async.wait_group 0;\n" ::: "memory");
    }
    __syncthreads();
    if (tt + 2 < NT) stage(tt + 2);

    const uint32_t sA = sm + (uint32_t)(tt % NSTAGES) * STAGE_B;
    const uint32_t sB = sA + A_BYTES;

#pragma unroll
    for (int ik = 0; ik < 4; ik++) {
      uint32_t a[4][4];
#pragma unroll
      for (int im = 0; im < 4; im++)
        ldsm_x4(a[im], sA + (uint32_t)(wm + im * 16 + laneRow) * LDA_B
                          + ik * 32 + laneHi * 16);
      uint32_t b[4][2];
#pragma unroll
      for (int jp = 0; jp < 2; jp++) {
        uint32_t r[4];
        ldsm_x4_t(r, sB + (uint32_t)(ik * 16 + laneRow) * LDB_B
                        + (uint32_t)(wn + jp * 16 + laneHi * 8) * 2);
        b[2 * jp][0] = r[0]; b[2 * jp][1] = r[1];
        b[2 * jp + 1][0] = r[2]; b[2 * jp + 1][1] = r[3];
      }
#pragma unroll
      for (int im = 0; im < 4; im++)
#pragma unroll
        for (int jn = 0; jn < 4; jn++)
          mma_f16(acc[im * 4 + jn], a[im], b[jn][0], b[jn][1]);
    }
    __syncthreads();
  }

  // epilogue
  float*  Cf = (float*)Cv;
  __half* Ch = (__half*)Cv;
#pragma unroll
  for (int im = 0; im < 4; im++) {
#pragma unroll
    for (int jn = 0; jn < 4; jn++) {
      const float* c = acc[im * 4 + jn];
      int r0 = brow + wm + im * 16 + g;
      int c0 = bcol + wn + jn * 8 + 2 * t;
#pragma unroll
      for (int u = 0; u < 4; u++) {
        int r = r0 + (u >> 1) * 8;
        int cc = c0 + (u & 1);
        if (cc < Nstore) {
          float val = c[u] + bias[cc];
          if (GELU) val = gelu_new(val);
          size_t idx = (size_t)r * Nstore + cc;
          if (OUTH) {
            Ch[idx] = __float2half(val);
          } else {
            if (ACCUM) val += Cf[idx];
            Cf[idx] = val;
          }
        }
      }
    }
  }
}

// -------------------- flash attention (fp32 math; fp16 z out) ------------
// q/k/v packed in one buffer, row stride 3072: q at +0, k at +1024, v at +2048.
__global__ __launch_bounds__(256) void attn_kernel(
    const float* __restrict__ qkv, __half* __restrict__ z) {
  const int b = blockIdx.z, h = blockIdx.y;
  const int q0 = blockIdx.x * 32;
  const int warp = threadIdx.x >> 5, lane = threadIdx.x & 31;
  const int rbase = warp * 4;

  __shared__ float Qs[32][D_HEAD + 1];
  __shared__ float Ks[32][D_HEAD + 1];
  __shared__ float Vs[32][D_HEAD + 1];

  for (int t = threadIdx.x; t < 32 * D_HEAD; t += 256) {
    int r = t >> 6, d = t & 63;
    Qs[r][d] = qkv[(size_t)(b * S_LEN + q0 + r) * QKV_N + h * D_HEAD + d] * 0.125f;
  }

  float m[4], lsum[4], acc0[4], acc1[4];
#pragma unroll
  for (int r = 0; r < 4; r++) {
    m[r] = -INFINITY; lsum[r] = 0.f; acc0[r] = 0.f; acc1[r] = 0.f;
  }

  const int kmax = q0 + 31;
  for (int kt = 0; kt <= kmax; kt += 32) {
    __syncthreads();
    for (int t = threadIdx.x; t < 32 * D_HEAD; t += 256) {
      int r = t >> 6, d = t & 63;
      size_t base = (size_t)(b * S_LEN + kt + r) * QKV_N + h * D_HEAD + d;
      Ks[r][d] = qkv[base + 1024];
      Vs[r][d] = qkv[base + 2048];
    }
    __syncthreads();

    float s[4] = {0.f, 0.f, 0.f, 0.f};
#pragma unroll 16
    for (int d = 0; d < D_HEAD; d++) {
      float kv = Ks[lane][d];
#pragma unroll
      for (int r = 0; r < 4; r++) s[r] += Qs[rbase + r][d] * kv;
    }

    float p[4];
#pragma unroll
    for (int r = 0; r < 4; r++) {
      int qrow = q0 + rbase + r;
      float sv = (kt + lane <= qrow) ? s[r] : -INFINITY;
      float mx = sv;
#pragma unroll
      for (int off = 16; off; off >>= 1)
        mx = fmaxf(mx, __shfl_xor_sync(0xffffffffu, mx, off));
      float mnew = fmaxf(m[r], mx);
      float corr = __expf(m[r] - mnew);
      p[r] = __expf(sv - mnew);
      m[r] = mnew;
      float psum = p[r];
#pragma unroll
      for (int off = 16; off; off >>= 1)
        psum += __shfl_xor_sync(0xffffffffu, psum, off);
      lsum[r] = lsum[r] * corr + psum;
      acc0[r] *= corr; acc1[r] *= corr;
    }
#pragma unroll 8
    for (int i = 0; i < 32; i++) {
      float v0 = Vs[i][lane], v1 = Vs[i][lane + 32];
#pragma unroll
      for (int r = 0; r < 4; r++) {
        float pi = __shfl_sync(0xffffffffu, p[r], i);
        acc0[r] += pi * v0;
        acc1[r] += pi * v1;
      }
    }
  }

#pragma unroll
  for (int r = 0; r < 4; r++) {
    size_t base = (size_t)(b * S_LEN + q0 + rbase + r) * D_MODEL + h * D_HEAD;
    float inv = 1.0f / lsum[r];
    z[base + lane]      = __float2half(acc0[r] * inv);
    z[base + lane + 32] = __float2half(acc1[r] * inv);
  }
}

// -------------------- driver --------------------
template<bool GELU, bool ACCUM, bool OUTH>
static void launch_hgemm(const __half* A, const __half* B, const float* bias,
                         void* C, int M, int K, int NB, int Nstore) {
  cudaFuncSetAttribute(hgemm<GELU, ACCUM, OUTH>,
                       cudaFuncAttributeMaxDynamicSharedMemorySize, GEMM_SMEM);
  dim3 grid(NB / 128, M / 128);
  hgemm<GELU, ACCUM, OUTH><<<grid, 256, GEMM_SMEM>>>(A, B, bias, C, M, K, NB, Nstore);
}

extern "C" void kernel_launch(void* const* d_in, const int* in_sizes, int n_in,
                              void* d_out, int out_size) {
  const int*   tokens = (const int*)  d_in[0];
  const float* W_E    = (const float*)d_in[1];
  const float* W_pos  = (const float*)d_in[2];
  const float* ln1_w  = (const float*)d_in[3];
  const float* ln1_b  = (const float*)d_in[4];
  const float* W_Q    = (const float*)d_in[5];
  const float* b_Q    = (const float*)d_in[6];
  const float* W_K    = (const float*)d_in[7];
  const float* b_K    = (const float*)d_in[8];
  const float* W_V    = (const float*)d_in[9];
  const float* b_V    = (const float*)d_in[10];
  const float* W_O    = (const float*)d_in[11];
  const float* b_O    = (const float*)d_in[12];
  const float* ln2_w  = (const float*)d_in[13];
  const float* ln2_b  = (const float*)d_in[14];
  const float* W_in   = (const float*)d_in[15];
  const float* b_in   = (const float*)d_in[16];
  const float* W_out  = (const float*)d_in[17];
  const float* b_out  = (const float*)d_in[18];
  const float* lnf_w  = (const float*)d_in[19];
  const float* lnf_b  = (const float*)d_in[20];
  const float* W_U    = (const float*)d_in[21];
  const float* b_U    = (const float*)d_in[22];
  float* out = (float*)d_out;

  float *resid, *qkv, *bqkv;
  __half *xh, *zh, *hh, *wqkv, *wo, *win, *wout, *wu;
  cudaGetSymbolAddress((void**)&resid, g_resid);
  cudaGetSymbolAddress((void**)&xh,    g_xh);
  cudaGetSymbolAddress((void**)&qkv,   g_qkv);
  cudaGetSymbolAddress((void**)&zh,    g_zh);
  cudaGetSymbolAddress((void**)&hh,    g_hh);
  cudaGetSymbolAddress((void**)&wqkv,  g_wqkv);
  cudaGetSymbolAddress((void**)&bqkv,  g_bqkv);
  cudaGetSymbolAddress((void**)&wo,    g_wo);
  cudaGetSymbolAddress((void**)&win,   g_win);
  cudaGetSymbolAddress((void**)&wout,  g_wout);
  cudaGetSymbolAddress((void**)&wu,    g_wu);

  // ---- weight conversion to fp16 ----
  conv_qkv<<<(N_LAYERS * D_MODEL * QKV_N) / 256, 256>>>(W_Q, W_K, W_V, wqkv);
  pack_bias_qkv<<<(N_LAYERS * QKV_N) / 256, 256>>>(b_Q, b_K, b_V, bqkv);
  for (int l = 0; l < N_LAYERS; l++) {
    size_t w1 = (size_t)l * D_MODEL * D_MODEL;
    size_t w2 = (size_t)l * D_MODEL * D_MLP;
    conv_plain<<<(D_MODEL * D_MODEL) / 256, 256>>>(W_O + w1,  wo + w1,  D_MODEL, D_MODEL);
    conv_plain<<<(D_MODEL * D_MLP) / 256, 256>>>(W_in + w2,  win + w2, D_MLP, D_MLP);
    conv_plain<<<(D_MLP * D_MODEL) / 256, 256>>>(W_out + w2, wout + w2, D_MODEL, D_MODEL);
  }
  conv_plain<<<((size_t)D_MODEL * N_VOCAB_PAD) / 256, 256>>>(W_U, wu, N_VOCAB, N_VOCAB_PAD);

  embed_kernel<<<N_TOKENS, 256>>>(tokens, W_E, W_pos, resid);

  dim3 gA(S_LEN / 32, N_HEADS, 2);

  for (int l = 0; l < N_LAYERS; l++) {
    size_t w1 = (size_t)l * D_MODEL * D_MODEL;
    size_t w2 = (size_t)l * D_MODEL * D_MLP;
    const float* l1w = ln1_w + (size_t)l * D_MODEL;
    const float* l1b = ln1_b + (size_t)l * D_MODEL;
    const float* l2w = ln2_w + (size_t)l * D_MODEL;
    const float* l2b = ln2_b + (size_t)l * D_MODEL;

    ln_kernel<<<N_TOKENS, 256>>>(resid, l1w, l1b, xh);
    // fused QKV: [4096,1024] x [1024,3072] -> qkv fp32
    launch_hgemm<false, false, false>(xh, wqkv + (size_t)l * D_MODEL * QKV_N,
                                      bqkv + (size_t)l * QKV_N, qkv,
                                      N_TOKENS, D_MODEL, QKV_N, QKV_N);
    attn_kernel<<<gA, 256>>>(qkv, zh);
    // resid += z @ W_O + b_O
    launch_hgemm<false, true, false>(zh, wo + w1, b_O + (size_t)l * D_MODEL, resid,
                                     N_TOKENS, D_MODEL, D_MODEL, D_MODEL);
    ln_kernel<<<N_TOKENS, 256>>>(resid, l2w, l2b, xh);
    // h = gelu(x @ W_in + b_in) -> fp16
    launch_hgemm<true, false, true>(xh, win + w2, b_in + (size_t)l * D_MLP, hh,
                                    N_TOKENS, D_MODEL, D_MLP, D_MLP);
    // resid += h @ W_out + b_out
    launch_hgemm<false, true, false>(hh, wout + w2, b_out + (size_t)l * D_MODEL, resid,
                                     N_TOKENS, D_MLP, D_MODEL, D_MODEL);
  }

  ln_kernel<<<N_TOKENS, 256>>>(resid, lnf_w, lnf_b, xh);
  launch_hgemm<false, false, false>(xh, wu, b_U, out,
                                    N_TOKENS, D_MODEL, N_VOCAB_PAD, N_VOCAB);
}

// round 7
// speedup vs baseline: 7.5824x; 1.9713x over previous
#include <cuda_runtime.h>
#include <cuda_fp16.h>
#include <cstdint>
#include <math.h>

#define S_LEN    2048
#define D_MODEL  1024
#define N_HEADS  16
#define D_HEAD   64
#define D_MLP    4096
#define N_LAYERS 4
#define N_VOCAB  50257
#define N_VOCAB_PAD 50432   // 394*128
#define N_TOKENS 4096       // B*S
#define QKV_N    3072

// -------------------- scratch --------------------
__device__ float  g_resid[N_TOKENS * D_MODEL];
__device__ __half g_xh   [N_TOKENS * D_MODEL];
__device__ __half g_qkvh [N_TOKENS * QKV_N];
__device__ __half g_zh   [N_TOKENS * D_MODEL];
__device__ __half g_hh   [N_TOKENS * D_MLP];
// fp16 weights, B layout [K][N] row-major (padded N where needed)
__device__ __half g_wqkv [N_LAYERS * D_MODEL * QKV_N];
__device__ float  g_bqkv [N_LAYERS * QKV_N];
__device__ __half g_wo   [N_LAYERS * D_MODEL * D_MODEL];
__device__ __half g_win  [N_LAYERS * D_MODEL * D_MLP];
__device__ __half g_wout [N_LAYERS * D_MLP * D_MODEL];
__device__ __half g_wu   [D_MODEL * N_VOCAB_PAD];

// -------------------- helpers --------------------
__device__ __forceinline__ float gelu_new(float x) {
  float u = 0.7978845608028654f * (x + 0.044715f * x * x * x);
  return 0.5f * x * (1.0f + tanhf(u));
}
__device__ __forceinline__ void ldsm_x4(uint32_t (&r)[4], uint32_t addr) {
  asm volatile("ldmatrix.sync.aligned.m8n8.x4.shared.b16 {%0,%1,%2,%3}, [%4];"
    : "=r"(r[0]), "=r"(r[1]), "=r"(r[2]), "=r"(r[3]) : "r"(addr));
}
__device__ __forceinline__ void ldsm_x4_t(uint32_t (&r)[4], uint32_t addr) {
  asm volatile("ldmatrix.sync.aligned.m8n8.x4.trans.shared.b16 {%0,%1,%2,%3}, [%4];"
    : "=r"(r[0]), "=r"(r[1]), "=r"(r[2]), "=r"(r[3]) : "r"(addr));
}
__device__ __forceinline__ void mma_f16(float (&c)[4], const uint32_t (&a)[4],
                                        const uint32_t b0, const uint32_t b1) {
  asm volatile("mma.sync.aligned.m16n8k16.row.col.f32.f16.f16.f32 "
    "{%0,%1,%2,%3}, {%4,%5,%6,%7}, {%8,%9}, {%0,%1,%2,%3};"
    : "+f"(c[0]), "+f"(c[1]), "+f"(c[2]), "+f"(c[3])
    : "r"(a[0]), "r"(a[1]), "r"(a[2]), "r"(a[3]), "r"(b0), "r"(b1));
}
__device__ __forceinline__ void cp_async16(uint32_t dst, const void* src) {
  asm volatile("cp.async.cg.shared.global [%0], [%1], 16;\n" :: "r"(dst), "l"(src));
}

// -------------------- weight conversion --------------------
__global__ __launch_bounds__(256) void conv_qkv(
    const float* __restrict__ WQ, const float* __restrict__ WK,
    const float* __restrict__ WV, __half* __restrict__ out) {
  size_t i = (size_t)blockIdx.x * 256 + threadIdx.x;   // L*1024*3072 total
  int n = (int)(i % QKV_N);
  size_t lk = i / QKV_N;
  int k = (int)(lk % D_MODEL);
  int l = (int)(lk / D_MODEL);
  int which = n >> 10, nn = n & 1023;
  int h = nn >> 6, dh = nn & 63;
  const float* W = (which == 0) ? WQ : ((which == 1) ? WK : WV);
  out[i] = __float2half(W[(((size_t)l * N_HEADS + h) * D_MODEL + k) * D_HEAD + dh]);
}
__global__ __launch_bounds__(256) void pack_bias_qkv(
    const float* __restrict__ bq, const float* __restrict__ bk,
    const float* __restrict__ bv, float* __restrict__ out) {
  int i = blockIdx.x * 256 + threadIdx.x;   // L*3072
  int n = i % QKV_N, l = i / QKV_N;
  const float* s = (n < 1024) ? bq : ((n < 2048) ? bk : bv);
  out[i] = s[l * 1024 + (n & 1023)];
}
__global__ __launch_bounds__(256) void conv_plain(
    const float* __restrict__ in, __half* __restrict__ out, int N, int Npad) {
  size_t i = (size_t)blockIdx.x * 256 + threadIdx.x;   // K*Npad total
  int n = (int)(i % Npad);
  size_t k = i / Npad;
  out[i] = __float2half((n < N) ? in[k * N + n] : 0.f);
}

// -------------------- embedding --------------------
__global__ __launch_bounds__(256) void embed_kernel(
    const int* __restrict__ tok, const float* __restrict__ WE,
    const float* __restrict__ Wp, float* __restrict__ out) {
  int row = blockIdx.x;
  int s = row & (S_LEN - 1);
  int t = threadIdx.x;
  int token = tok[row];
  float4 e = reinterpret_cast<const float4*>(WE + (size_t)token * D_MODEL)[t];
  float4 p = reinterpret_cast<const float4*>(Wp + (size_t)s * D_MODEL)[t];
  float4 r;
  r.x = e.x + p.x; r.y = e.y + p.y; r.z = e.z + p.z; r.w = e.w + p.w;
  reinterpret_cast<float4*>(out + (size_t)row * D_MODEL)[t] = r;
}

// -------------------- layernorm (fp32 in, fp16 out) --------------------
__global__ __launch_bounds__(256) void ln_kernel(
    const float* __restrict__ in, const float* __restrict__ w,
    const float* __restrict__ b, __half* __restrict__ out) {
  int row = blockIdx.x;
  int t = threadIdx.x;
  float4 v = reinterpret_cast<const float4*>(in + (size_t)row * D_MODEL)[t];
  float s  = v.x + v.y + v.z + v.w;
  float ss = v.x*v.x + v.y*v.y + v.z*v.z + v.w*v.w;
#pragma unroll
  for (int off = 16; off; off >>= 1) {
    s  += __shfl_xor_sync(0xffffffffu, s,  off);
    ss += __shfl_xor_sync(0xffffffffu, ss, off);
  }
  __shared__ float shs[8], shss[8];
  int wid = t >> 5;
  if ((t & 31) == 0) { shs[wid] = s; shss[wid] = ss; }
  __syncthreads();
  float tot = 0.f, tots = 0.f;
#pragma unroll
  for (int i = 0; i < 8; i++) { tot += shs[i]; tots += shss[i]; }
  float mean = tot * (1.0f / D_MODEL);
  float var  = tots * (1.0f / D_MODEL) - mean * mean;
  float rstd = rsqrtf(var + 1e-5f);
  float4 wv = reinterpret_cast<const float4*>(w)[t];
  float4 bv = reinterpret_cast<const float4*>(b)[t];
  float ox = (v.x - mean) * rstd * wv.x + bv.x;
  float oy = (v.y - mean) * rstd * wv.y + bv.y;
  float oz = (v.z - mean) * rstd * wv.z + bv.z;
  float ow = (v.w - mean) * rstd * wv.w + bv.w;
  __half2* o2 = reinterpret_cast<__half2*>(out + (size_t)row * D_MODEL);
  o2[2 * t]     = __floats2half2_rn(ox, oy);
  o2[2 * t + 1] = __floats2half2_rn(oz, ow);
}

// -------------------- FP16 tensor-core GEMM --------------------
#define KT        64
#define LDA_B     144
#define LDB_B     272
#define A_BYTES   (128 * LDA_B)
#define B_BYTES   (KT * LDB_B)
#define STAGE_B   (A_BYTES + B_BYTES)
#define NSTAGES   3
#define GEMM_SMEM (NSTAGES * STAGE_B)

template<bool GELU, bool ACCUM, bool OUTH>
__global__ __launch_bounds__(256) void hgemm(
    const __half* __restrict__ A, const __half* __restrict__ B,
    const float* __restrict__ bias, void* __restrict__ Cv,
    int M, int K, int NB, int Nstore) {
  extern __shared__ __align__(16) char smem[];
  const uint32_t sm = (uint32_t)__cvta_generic_to_shared(smem);

  const int tid  = threadIdx.x;
  const int lane = tid & 31, warp = tid >> 5;
  const int wm = (warp >> 2) * 64;
  const int wn = (warp & 3) * 32;
  const int g = lane >> 2, t = lane & 3;
  const int brow = blockIdx.y * 128, bcol = blockIdx.x * 128;
  const uint32_t laneRow = lane & 15, laneHi = lane >> 4;

  float acc[16][4];
#pragma unroll
  for (int i = 0; i < 16; i++)
#pragma unroll
    for (int j = 0; j < 4; j++) acc[i][j] = 0.f;

  const int NT = K / KT;

  auto stage = [&](int tt) {
    const int k0 = tt * KT;
    const uint32_t sA = sm + (uint32_t)(tt % NSTAGES) * STAGE_B;
    const uint32_t sB = sA + A_BYTES;
    {
      int slot = tid;
#pragma unroll
      for (int i = 0; i < 4; i++) {
        int r = slot >> 3, ch = slot & 7;
        cp_async16(sA + (uint32_t)r * LDA_B + ch * 16,
                   A + (size_t)(brow + r) * K + k0 + ch * 8);
        slot += 256;
      }
    }
    {
      int slot = tid;
#pragma unroll
      for (int i = 0; i < 4; i++) {
        int r = slot >> 4, ch = slot & 15;
        cp_async16(sB + (uint32_t)r * LDB_B + ch * 16,
                   B + (size_t)(k0 + r) * NB + bcol + ch * 8);
        slot += 256;
      }
    }
    asm volatile("cp.async.commit_group;\n" ::: "memory");
  };

  stage(0);
  if (NT > 1) stage(1);

  for (int tt = 0; tt < NT; tt++) {
    if (tt + 1 < NT) {
      asm volatile("cp.async.wait_group 1;\n" ::: "memory");
    } else {
      asm volatile("cp.async.wait_group 0;\n" ::: "memory");
    }
    __syncthreads();
    if (tt + 2 < NT) stage(tt + 2);

    const uint32_t sA = sm + (uint32_t)(tt % NSTAGES) * STAGE_B;
    const uint32_t sB = sA + A_BYTES;

#pragma unroll
    for (int ik = 0; ik < 4; ik++) {
      uint32_t a[4][4];
#pragma unroll
      for (int im = 0; im < 4; im++)
        ldsm_x4(a[im], sA + (uint32_t)(wm + im * 16 + laneRow) * LDA_B
                          + ik * 32 + laneHi * 16);
      uint32_t b[4][2];
#pragma unroll
      for (int jp = 0; jp < 2; jp++) {
        uint32_t r[4];
        ldsm_x4_t(r, sB + (uint32_t)(ik * 16 + laneRow) * LDB_B
                        + (uint32_t)(wn + jp * 16 + laneHi * 8) * 2);
        b[2 * jp][0] = r[0]; b[2 * jp][1] = r[1];
        b[2 * jp + 1][0] = r[2]; b[2 * jp + 1][1] = r[3];
      }
#pragma unroll
      for (int im = 0; im < 4; im++)
#pragma unroll
        for (int jn = 0; jn < 4; jn++)
          mma_f16(acc[im * 4 + jn], a[im], b[jn][0], b[jn][1]);
    }
    __syncthreads();
  }

  float*  Cf = (float*)Cv;
  __half* Ch = (__half*)Cv;
#pragma unroll
  for (int im = 0; im < 4; im++) {
#pragma unroll
    for (int jn = 0; jn < 4; jn++) {
      const float* c = acc[im * 4 + jn];
      int r0 = brow + wm + im * 16 + g;
      int c0 = bcol + wn + jn * 8 + 2 * t;
#pragma unroll
      for (int u = 0; u < 4; u++) {
        int r = r0 + (u >> 1) * 8;
        int cc = c0 + (u & 1);
        if (cc < Nstore) {
          float val = c[u] + bias[cc];
          if (GELU) val = gelu_new(val);
          size_t idx = (size_t)r * Nstore + cc;
          if (OUTH) {
            Ch[idx] = __float2half(val);
          } else {
            if (ACCUM) val += Cf[idx];
            Cf[idx] = val;
          }
        }
      }
    }
  }
}

// -------------------- tensor-core flash attention --------------------
// qkv half [token][3072]: q +0, k +1024, v +2048. z half [token][1024].
// CTA: 64 queries x one (b,h); 4 warps x 16 rows; K/V tiles 64 keys, 2 buffers.
#define ATT_LD 144   // bytes per smem row (72 halves)
__global__ __launch_bounds__(128) void attn_tc(
    const __half* __restrict__ qkv, __half* __restrict__ z) {
  const int b = blockIdx.z, h = blockIdx.y;
  const int q0 = (gridDim.x - 1 - blockIdx.x) * 64;   // heavy CTAs first
  const int tid = threadIdx.x;
  const int warp = tid >> 5, lane = tid & 31;
  const int g = lane >> 2, t = lane & 3;

  __shared__ __align__(16) __half sQ[64 * 72];
  __shared__ __align__(16) __half sK[2][64 * 72];
  __shared__ __align__(16) __half sV[2][64 * 72];
  const uint32_t qb = (uint32_t)__cvta_generic_to_shared(sQ);
  const uint32_t kb0 = (uint32_t)__cvta_generic_to_shared(sK[0]);
  const uint32_t kb1 = (uint32_t)__cvta_generic_to_shared(sK[1]);
  const uint32_t vb0 = (uint32_t)__cvta_generic_to_shared(sV[0]);
  const uint32_t vb1 = (uint32_t)__cvta_generic_to_shared(sV[1]);

  // load Q tile (64 rows x 64 halves)
  for (int slot = tid; slot < 512; slot += 128) {
    int r = slot >> 3, c = slot & 7;
    *reinterpret_cast<uint4*>(&sQ[r * 72 + c * 8]) =
      *reinterpret_cast<const uint4*>(
        qkv + (size_t)(b * S_LEN + q0 + r) * QKV_N + h * D_HEAD + c * 8);
  }
  __syncthreads();

  // Q fragments: qf[ik] covers k = ik*16..+15
  uint32_t qf[4][4];
#pragma unroll
  for (int ik = 0; ik < 4; ik++)
    ldsm_x4(qf[ik], qb + (uint32_t)(warp * 16 + (lane & 15)) * ATT_LD
                       + ik * 32 + (lane >> 4) * 16);

  const int row0 = q0 + warp * 16 + g;
  const int row1 = row0 + 8;

  float m0 = -INFINITY, m1 = -INFINITY, l0 = 0.f, l1 = 0.f;
  float oacc[8][4];
#pragma unroll
  for (int i = 0; i < 8; i++)
#pragma unroll
    for (int j = 0; j < 4; j++) oacc[i][j] = 0.f;

  const int ntiles = (q0 >> 6) + 1;

  auto stageKV = [&](int tile) {
    const int kt = tile * 64;
    const uint32_t kd = (tile & 1) ? kb1 : kb0;
    const uint32_t vd = (tile & 1) ? vb1 : vb0;
    for (int slot = tid; slot < 512; slot += 128) {
      int r = slot >> 3, c = slot & 7;
      const __half* src = qkv + (size_t)(b * S_LEN + kt + r) * QKV_N
                              + 1024 + h * D_HEAD + c * 8;
      cp_async16(kd + (uint32_t)r * ATT_LD + c * 16, src);
      cp_async16(vd + (uint32_t)r * ATT_LD + c * 16, src + 1024);
    }
    asm volatile("cp.async.commit_group;\n" ::: "memory");
  };

  stageKV(0);

  for (int tile = 0; tile < ntiles; tile++) {
    asm volatile("cp.async.wait_group 0;\n" ::: "memory");
    __syncthreads();
    if (tile + 1 < ntiles) stageKV(tile + 1);

    const uint32_t kd = (tile & 1) ? kb1 : kb0;
    const uint32_t vd = (tile & 1) ? vb1 : vb0;
    const int kt = tile * 64;

    // S = Q @ K^T : 8 n-tiles of 8 keys
    float sacc[8][4];
#pragma unroll
    for (int j = 0; j < 8; j++) {
#pragma unroll
      for (int u = 0; u < 4; u++) sacc[j][u] = 0.f;
      uint32_t bk0[4], bk1[4];
      uint32_t base = kd + (uint32_t)(j * 8 + (lane & 7)) * ATT_LD + (lane >> 3) * 16;
      ldsm_x4(bk0, base);        // dh 0-31
      ldsm_x4(bk1, base + 64);   // dh 32-63
      mma_f16(sacc[j], qf[0], bk0[0], bk0[1]);
      mma_f16(sacc[j], qf[1], bk0[2], bk0[3]);
      mma_f16(sacc[j], qf[2], bk1[0], bk1[1]);
      mma_f16(sacc[j], qf[3], bk1[2], bk1[3]);
    }

    // mask + scale, tile row-max
    float tmx0 = -1e30f, tmx1 = -1e30f;
#pragma unroll
    for (int j = 0; j < 8; j++) {
      int kbase = kt + j * 8 + 2 * t;
      sacc[j][0] = (kbase     <= row0) ? sacc[j][0] * 0.125f : -1e30f;
      sacc[j][1] = (kbase + 1 <= row0) ? sacc[j][1] * 0.125f : -1e30f;
      sacc[j][2] = (kbase     <= row1) ? sacc[j][2] * 0.125f : -1e30f;
      sacc[j][3] = (kbase + 1 <= row1) ? sacc[j][3] * 0.125f : -1e30f;
      tmx0 = fmaxf(tmx0, fmaxf(sacc[j][0], sacc[j][1]));
      tmx1 = fmaxf(tmx1, fmaxf(sacc[j][2], sacc[j][3]));
    }
#pragma unroll
    for (int off = 1; off <= 2; off <<= 1) {
      tmx0 = fmaxf(tmx0, __shfl_xor_sync(0xffffffffu, tmx0, off));
      tmx1 = fmaxf(tmx1, __shfl_xor_sync(0xffffffffu, tmx1, off));
    }
    float mn0 = fmaxf(m0, tmx0), mn1 = fmaxf(m1, tmx1);
    float corr0 = __expf(m0 - mn0), corr1 = __expf(m1 - mn1);
    m0 = mn0; m1 = mn1;

    // P = exp(S - m), pack to half fragments
    uint32_t pf[8][2];
    float sum0 = 0.f, sum1 = 0.f;
#pragma unroll
    for (int j = 0; j < 8; j++) {
      float p0 = __expf(sacc[j][0] - mn0);
      float p1 = __expf(sacc[j][1] - mn0);
      float p2 = __expf(sacc[j][2] - mn1);
      float p3 = __expf(sacc[j][3] - mn1);
      sum0 += p0 + p1; sum1 += p2 + p3;
      __half2 h01 = __floats2half2_rn(p0, p1);
      __half2 h23 = __floats2half2_rn(p2, p3);
      pf[j][0] = *reinterpret_cast<uint32_t*>(&h01);
      pf[j][1] = *reinterpret_cast<uint32_t*>(&h23);
    }
#pragma unroll
    for (int off = 1; off <= 2; off <<= 1) {
      sum0 += __shfl_xor_sync(0xffffffffu, sum0, off);
      sum1 += __shfl_xor_sync(0xffffffffu, sum1, off);
    }
    l0 = l0 * corr0 + sum0;
    l1 = l1 * corr1 + sum1;
#pragma unroll
    for (int np = 0; np < 8; np++) {
      oacc[np][0] *= corr0; oacc[np][1] *= corr0;
      oacc[np][2] *= corr1; oacc[np][3] *= corr1;
    }

    // O += P @ V : 4 k-steps (16 keys) x 4 dh-pairs (16 cols)
#pragma unroll
    for (int kk = 0; kk < 4; kk++) {
      uint32_t a[4] = { pf[2 * kk][0], pf[2 * kk][1],
                        pf[2 * kk + 1][0], pf[2 * kk + 1][1] };
#pragma unroll
      for (int np = 0; np < 4; np++) {
        uint32_t r[4];
        ldsm_x4_t(r, vd + (uint32_t)(kk * 16 + (lane & 15)) * ATT_LD
                        + np * 32 + (lane >> 4) * 16);
        mma_f16(oacc[2 * np], a, r[0], r[1]);
        mma_f16(oacc[2 * np + 1], a, r[2], r[3]);
      }
    }
    __syncthreads();
  }

  const float inv0 = 1.0f / l0, inv1 = 1.0f / l1;
#pragma unroll
  for (int np = 0; np < 8; np++) {
    int col = h * D_HEAD + np * 8 + 2 * t;
    __half2 lo = __floats2half2_rn(oacc[np][0] * inv0, oacc[np][1] * inv0);
    __half2 hi = __floats2half2_rn(oacc[np][2] * inv1, oacc[np][3] * inv1);
    *reinterpret_cast<__half2*>(&z[(size_t)(b * S_LEN + row0) * D_MODEL + col]) = lo;
    *reinterpret_cast<__half2*>(&z[(size_t)(b * S_LEN + row1) * D_MODEL + col]) = hi;
  }
}

// -------------------- driver --------------------
template<bool GELU, bool ACCUM, bool OUTH>
static void launch_hgemm(const __half* A, const __half* B, const float* bias,
                         void* C, int M, int K, int NB, int Nstore) {
  cudaFuncSetAttribute(hgemm<GELU, ACCUM, OUTH>,
                       cudaFuncAttributeMaxDynamicSharedMemorySize, GEMM_SMEM);
  dim3 grid(NB / 128, M / 128);
  hgemm<GELU, ACCUM, OUTH><<<grid, 256, GEMM_SMEM>>>(A, B, bias, C, M, K, NB, Nstore);
}

extern "C" void kernel_launch(void* const* d_in, const int* in_sizes, int n_in,
                              void* d_out, int out_size) {
  const int*   tokens = (const int*)  d_in[0];
  const float* W_E    = (const float*)d_in[1];
  const float* W_pos  = (const float*)d_in[2];
  const float* ln1_w  = (const float*)d_in[3];
  const float* ln1_b  = (const float*)d_in[4];
  const float* W_Q    = (const float*)d_in[5];
  const float* b_Q    = (const float*)d_in[6];
  const float* W_K    = (const float*)d_in[7];
  const float* b_K    = (const float*)d_in[8];
  const float* W_V    = (const float*)d_in[9];
  const float* b_V    = (const float*)d_in[10];
  const float* W_O    = (const float*)d_in[11];
  const float* b_O    = (const float*)d_in[12];
  const float* ln2_w  = (const float*)d_in[13];
  const float* ln2_b  = (const float*)d_in[14];
  const float* W_in   = (const float*)d_in[15];
  const float* b_in   = (const float*)d_in[16];
  const float* W_out  = (const float*)d_in[17];
  const float* b_out  = (const float*)d_in[18];
  const float* lnf_w  = (const float*)d_in[19];
  const float* lnf_b  = (const float*)d_in[20];
  const float* W_U    = (const float*)d_in[21];
  const float* b_U    = (const float*)d_in[22];
  float* out = (float*)d_out;

  float *resid, *bqkv;
  __half *xh, *qkvh, *zh, *hh, *wqkv, *wo, *win, *wout, *wu;
  cudaGetSymbolAddress((void**)&resid, g_resid);
  cudaGetSymbolAddress((void**)&xh,    g_xh);
  cudaGetSymbolAddress((void**)&qkvh,  g_qkvh);
  cudaGetSymbolAddress((void**)&zh,    g_zh);
  cudaGetSymbolAddress((void**)&hh,    g_hh);
  cudaGetSymbolAddress((void**)&wqkv,  g_wqkv);
  cudaGetSymbolAddress((void**)&bqkv,  g_bqkv);
  cudaGetSymbolAddress((void**)&wo,    g_wo);
  cudaGetSymbolAddress((void**)&win,   g_win);
  cudaGetSymbolAddress((void**)&wout,  g_wout);
  cudaGetSymbolAddress((void**)&wu,    g_wu);

  conv_qkv<<<(N_LAYERS * D_MODEL * QKV_N) / 256, 256>>>(W_Q, W_K, W_V, wqkv);
  pack_bias_qkv<<<(N_LAYERS * QKV_N) / 256, 256>>>(b_Q, b_K, b_V, bqkv);
  for (int l = 0; l < N_LAYERS; l++) {
    size_t w1 = (size_t)l * D_MODEL * D_MODEL;
    size_t w2 = (size_t)l * D_MODEL * D_MLP;
    conv_plain<<<(D_MODEL * D_MODEL) / 256, 256>>>(W_O + w1,  wo + w1,  D_MODEL, D_MODEL);
    conv_plain<<<(D_MODEL * D_MLP) / 256, 256>>>(W_in + w2,  win + w2, D_MLP, D_MLP);
    conv_plain<<<(D_MLP * D_MODEL) / 256, 256>>>(W_out + w2, wout + w2, D_MODEL, D_MODEL);
  }
  conv_plain<<<((size_t)D_MODEL * N_VOCAB_PAD) / 256, 256>>>(W_U, wu, N_VOCAB, N_VOCAB_PAD);

  embed_kernel<<<N_TOKENS, 256>>>(tokens, W_E, W_pos, resid);

  dim3 gA(S_LEN / 64, N_HEADS, 2);

  for (int l = 0; l < N_LAYERS; l++) {
    size_t w1 = (size_t)l * D_MODEL * D_MODEL;
    size_t w2 = (size_t)l * D_MODEL * D_MLP;
    const float* l1w = ln1_w + (size_t)l * D_MODEL;
    const float* l1b = ln1_b + (size_t)l * D_MODEL;
    const float* l2w = ln2_w + (size_t)l * D_MODEL;
    const float* l2b = ln2_b + (size_t)l * D_MODEL;

    ln_kernel<<<N_TOKENS, 256>>>(resid, l1w, l1b, xh);
    // fused QKV -> fp16
    launch_hgemm<false, false, true>(xh, wqkv + (size_t)l * D_MODEL * QKV_N,
                                     bqkv + (size_t)l * QKV_N, qkvh,
                                     N_TOKENS, D_MODEL, QKV_N, QKV_N);
    attn_tc<<<gA, 128>>>(qkvh, zh);
    // resid += z @ W_O + b_O
    launch_hgemm<false, true, false>(zh, wo + w1, b_O + (size_t)l * D_MODEL, resid,
                                     N_TOKENS, D_MODEL, D_MODEL, D_MODEL);
    ln_kernel<<<N_TOKENS, 256>>>(resid, l2w, l2b, xh);
    // h = gelu(x @ W_in + b_in) -> fp16
    launch_hgemm<true, false, true>(xh, win + w2, b_in + (size_t)l * D_MLP, hh,
                                    N_TOKENS, D_MODEL, D_MLP, D_MLP);
    // resid += h @ W_out + b_out
    launch_hgemm<false, true, false>(hh, wout + w2, b_out + (size_t)l * D_MODEL, resid,
                                     N_TOKENS, D_MLP, D_MODEL, D_MODEL);
  }

  ln_kernel<<<N_TOKENS, 256>>>(resid, lnf_w, lnf_b, xh);
  launch_hgemm<false, false, false>(xh, wu, b_U, out,
                                    N_TOKENS, D_MODEL, N_VOCAB_PAD, N_VOCAB);
}